// round 14
// baseline (speedup 1.0000x reference)
#include <cuda_runtime.h>
#include <cstdint>

#define En 4096
#define Bn 8
#define HEADS 32
#define Dh 128
#define CK 128               // k-floats per chunk
#define RB 16                // W rows per block
#define SN 4                 // pipeline stages
#define KS 2                 // k-splits per output row
#define KCH (En / (CK * KS)) // 16 chunks per block

typedef unsigned long long u64;

// qkv partials: [ks][proj][b][4096]
__device__ __align__(16) float g_part[KS * 3 * Bn * En];
__device__ __align__(16) float g_o[Bn * En];

__device__ __forceinline__ void fma2(u64 &d, u64 a, u64 b) {
    asm("fma.rn.f32x2 %0, %1, %2, %0;" : "+l"(d) : "l"(a), "l"(b));
}
__device__ __forceinline__ float2 unpack2(u64 v) {
    float2 r; asm("mov.b64 {%0,%1}, %2;" : "=f"(r.x), "=f"(r.y) : "l"(v)); return r;
}
__device__ __forceinline__ void cp16(uint32_t saddr, const float* g) {
    asm volatile("cp.async.cg.shared.global.L2::256B [%0], [%1], 16;" :: "r"(saddr), "l"(g));
}
__device__ __forceinline__ void gdc_wait() {
    asm volatile("griddepcontrol.wait;" ::: "memory");
}
__device__ __forceinline__ void gdc_launch_dep() {
    asm volatile("griddepcontrol.launch_dependents;" ::: "memory");
}
#define COMMIT() asm volatile("cp.async.commit_group;")
#define WAITG(n) asm volatile("cp.async.wait_group %0;" :: "n"(n))

struct SmemTiles {
    float w[SN][RB][CK];  // 32KB
    float x[SN][Bn][CK];  // 16KB
};                        // 48KB

// butterfly transpose-reduce of 32 per-thread partials -> 1 value/lane
__device__ __forceinline__ float reduce32(u64* acc, int lane, int& r_out, int& b_out) {
    float vals[32];
#pragma unroll
    for (int i = 0; i < 32; ++i) {
        float2 p = unpack2(acc[i]);
        vals[i] = p.x + p.y;
    }
    int n = 32;
#pragma unroll
    for (int m = 1; m <= 16; m <<= 1) {
        n >>= 1;
        bool up = (lane & m) != 0;
#pragma unroll
        for (int i = 0; i < n; ++i) {
            float keep = up ? vals[i + n] : vals[i];
            float send = up ? vals[i] : vals[i + n];
            keep += __shfl_xor_sync(0xffffffffu, send, m);
            vals[i] = keep;
        }
    }
    int j = ((lane & 1) << 4) | ((lane & 2) << 2) | (lane & 4) |
            ((lane >> 2) & 2) | ((lane >> 4) & 1);
    r_out = j >> 3;
    b_out = j & 7;
    return vals[0];
}

// ---------- shared compute core ----------
struct CopyDesc {
    const float* wg[4]; uint32_t wsm[4];
    const float* xg[2]; uint32_t xsm[2];
};

__device__ __forceinline__ void make_desc(CopyDesc& cd, SmemTiles& sm,
                                          const float* W, const float* X,
                                          int row0, int k0, int t) {
    uint32_t swb = (uint32_t)__cvta_generic_to_shared(&sm.w[0][0][0]);
    uint32_t sxb = (uint32_t)__cvta_generic_to_shared(&sm.x[0][0][0]);
#pragma unroll
    for (int p = 0; p < 4; ++p) {
        int u = p * 128 + t, r = u >> 5, c = u & 31;
        cd.wg[p] = W + (size_t)(row0 + r) * En + k0 + c * 4;
        cd.wsm[p] = swb + u * 16;
    }
#pragma unroll
    for (int p = 0; p < 2; ++p) {
        int u = p * 128 + t, b = u >> 5, c = u & 31;
        cd.xg[p] = X + (size_t)b * En + k0 + c * 4;
        cd.xsm[p] = sxb + u * 16;
    }
}
__device__ __forceinline__ void issue_w(CopyDesc& cd, int st, int kc) {
    int koff = kc * CK;
    uint32_t wo = st * (RB * CK * 4);
#pragma unroll
    for (int p = 0; p < 4; ++p) cp16(cd.wsm[p] + wo, cd.wg[p] + koff);
}
__device__ __forceinline__ void issue_x(CopyDesc& cd, int st, int kc) {
    int koff = kc * CK;
    uint32_t xo = st * (Bn * CK * 4);
#pragma unroll
    for (int p = 0; p < 2; ++p) cp16(cd.xsm[p] + xo, cd.xg[p] + koff);
}
__device__ __forceinline__ void consume_chunk(SmemTiles& sm, u64* acc,
                                              int st, int warp, int lane) {
    longlong2 wv[4];
#pragma unroll
    for (int r = 0; r < 4; ++r)
        wv[r] = *reinterpret_cast<const longlong2*>(&sm.w[st][warp * 4 + r][lane * 4]);
#pragma unroll
    for (int b = 0; b < 8; ++b) {
        longlong2 xv = *reinterpret_cast<const longlong2*>(&sm.x[st][b][lane * 4]);
#pragma unroll
        for (int r = 0; r < 4; ++r) {
            fma2(acc[r * 8 + b], (u64)wv[r].x, (u64)xv.x);
            fma2(acc[r * 8 + b], (u64)wv[r].y, (u64)xv.y);
        }
    }
}

// ---------- qkv: pipelined, direct partial store ----------
__global__ void __launch_bounds__(128, 4)
qkv_kernel(const float* __restrict__ Wq, const float* __restrict__ Wk,
           const float* __restrict__ Wv, const float* __restrict__ x) {
    gdc_launch_dep();
    __shared__ SmemTiles sm;
    const int t = threadIdx.x, warp = t >> 5, lane = t & 31;
    int rb = blockIdx.x >> 1, ks = blockIdx.x & 1;
    int row0 = rb * RB, k0 = ks * (En / KS);
    const float* W = (blockIdx.y == 0) ? Wq : ((blockIdx.y == 1) ? Wk : Wv);
    float* out = g_part + (size_t)(ks * 3 + blockIdx.y) * Bn * En;

    CopyDesc cd;
    make_desc(cd, sm, W, x, row0, k0, t);

#pragma unroll
    for (int s = 0; s < SN - 1; ++s) { issue_w(cd, s, s); issue_x(cd, s, s); COMMIT(); }

    u64 acc[32];
#pragma unroll
    for (int i = 0; i < 32; ++i) acc[i] = 0ull;

    for (int i = 0; i < KCH; ++i) {
        WAITG(SN - 2);
        __syncthreads();
        int nk = i + SN - 1;
        if (nk < KCH) { issue_w(cd, nk % SN, nk); issue_x(cd, nk % SN, nk); COMMIT(); }
        else COMMIT();
        consume_chunk(sm, acc, i % SN, warp, lane);
    }

    int r, b;
    float v = reduce32(acc, lane, r, b);
    out[(size_t)b * En + row0 + warp * 4 + r] = v;
}

// ---------- attn: PDL; zeroes d_out pre-wait; sums partials ----------
__global__ void __launch_bounds__(256)
attn_kernel(float* __restrict__ out) {
    gdc_launch_dep();
    int gtid = blockIdx.x * blockDim.x + threadIdx.x;
    reinterpret_cast<float4*>(out)[gtid] = make_float4(0.f, 0.f, 0.f, 0.f);

    gdc_wait();  // all qkv partials written

    int warp = gtid >> 5;
    int lane = gtid & 31;
    int b = warp >> 5;
    int h = warp & 31;

    float4 qv = make_float4(0.f, 0.f, 0.f, 0.f);
    float4 kv = qv, vv = qv;
#pragma unroll
    for (int ksp = 0; ksp < KS; ++ksp) {
        size_t base = (size_t)(ksp * 3) * Bn * En + (size_t)b * En + h * Dh + lane * 4;
        float4 a0 = *reinterpret_cast<const float4*>(g_part + base);
        float4 a1 = *reinterpret_cast<const float4*>(g_part + base + (size_t)Bn * En);
        float4 a2 = *reinterpret_cast<const float4*>(g_part + base + (size_t)2 * Bn * En);
        qv.x += a0.x; qv.y += a0.y; qv.z += a0.z; qv.w += a0.w;
        kv.x += a1.x; kv.y += a1.y; kv.z += a1.z; kv.w += a1.w;
        vv.x += a2.x; vv.y += a2.y; vv.z += a2.z; vv.w += a2.w;
    }

    float sq = qv.x + qv.y + qv.z + qv.w;
    float dp = qv.x * kv.x + qv.y * kv.y + qv.z * kv.z + qv.w * kv.w;
#pragma unroll
    for (int m = 16; m >= 1; m >>= 1) {
        sq += __shfl_xor_sync(0xffffffffu, sq, m);
        dp += __shfl_xor_sync(0xffffffffu, dp, m);
    }

    const float scale = 0.08838834764831845f;  // 1/sqrt(128)
    float s0 = sq * scale;
    float sL = dp * scale;
    float mx = fmaxf(s0, sL);
    float e0 = expf(s0 - mx);
    float eL = expf(sL - mx);
    float inv = 1.0f / (4095.0f * e0 + eL);
    float c1 = 4095.0f * e0 * inv;
    float c2 = eL * inv;

    float4* o4 = reinterpret_cast<float4*>(g_o + b * En + h * Dh);
    o4[lane] = make_float4(c1 + c2 * vv.x, c1 + c2 * vv.y,
                           c1 + c2 * vv.z, c1 + c2 * vv.w);
}

// ---------- oproj: PDL; W prologue pre-wait, x after ----------
__global__ void __launch_bounds__(128, 4)
oproj_kernel(const float* __restrict__ Wo, float* __restrict__ out) {
    __shared__ SmemTiles sm;
    const int t = threadIdx.x, warp = t >> 5, lane = t & 31;
    int rb = blockIdx.x >> 1, ks = blockIdx.x & 1;
    int row0 = rb * RB, k0 = ks * (En / KS);

    CopyDesc cd;
    make_desc(cd, sm, Wo, g_o, row0, k0, t);

    // W prologue: 3 groups (independent of upstream)
#pragma unroll
    for (int s = 0; s < SN - 1; ++s) { issue_w(cd, s, s); COMMIT(); }

    gdc_wait();  // attn done -> g_o and zeroed out visible

    // x prologue: 3 more groups
#pragma unroll
    for (int s = 0; s < SN - 1; ++s) { issue_x(cd, s, s); COMMIT(); }

    u64 acc[32];
#pragma unroll
    for (int i = 0; i < 32; ++i) acc[i] = 0ull;

    // groups: [W0 W1 W2 X0 X1 X2 WX3 ... WX15]; stage i needs first 4+i groups
    // complete; committed before wait at iter i = 6+min(i, KCH-3)
    // -> pending allowed: 2 (i<KCH-2), 1 (i==KCH-2), 0 (last).
    for (int i = 0; i < KCH; ++i) {
        if (i < KCH - 2) WAITG(2);
        else if (i == KCH - 2) WAITG(1);
        else WAITG(0);
        __syncthreads();
        int nk = i + SN - 1;
        if (nk < KCH) { issue_w(cd, nk % SN, nk); issue_x(cd, nk % SN, nk); COMMIT(); }
        consume_chunk(sm, acc, i % SN, warp, lane);
    }

    int r, b;
    float v = reduce32(acc, lane, r, b);
    atomicAdd(&out[(size_t)b * En + row0 + warp * 4 + r], v);
}

extern "C" void kernel_launch(void* const* d_in, const int* in_sizes, int n_in,
                              void* d_out, int out_size) {
    const float* x  = (const float*)d_in[0];
    const float* Wq = (const float*)d_in[1];
    const float* Wk = (const float*)d_in[2];
    const float* Wv = (const float*)d_in[3];
    const float* Wo = (const float*)d_in[4];
    float* out = (float*)d_out;

    dim3 gq(512, 3);
    qkv_kernel<<<gq, 128>>>(Wq, Wk, Wv, x);

    cudaLaunchAttribute at[1];
    at[0].id = cudaLaunchAttributeProgrammaticStreamSerialization;
    at[0].val.programmaticStreamSerializationAllowed = 1;

    cudaLaunchConfig_t cfg_attn = {};
    cfg_attn.gridDim = dim3(32);
    cfg_attn.blockDim = dim3(256);
    cfg_attn.attrs = at;
    cfg_attn.numAttrs = 1;
    cudaLaunchKernelEx(&cfg_attn, attn_kernel, out);

    cudaLaunchConfig_t cfg_opj = {};
    cfg_opj.gridDim = dim3(512);
    cfg_opj.blockDim = dim3(128);
    cfg_opj.attrs = at;
    cfg_opj.numAttrs = 1;
    cudaLaunchKernelEx(&cfg_opj, oproj_kernel, (const float*)Wo, out);
}